// round 1
// baseline (speedup 1.0000x reference)
#include <cuda_runtime.h>
#include <math.h>

#define NN    50000
#define EE    800000
#define INDIM 300
#define HID   128
#define NL    4
#define LD    ((NL + 1) * HID)   // 640

// ---------------- scratch (device globals; no runtime alloc) ----------------
__device__ float g_REPS[(size_t)NN * LD];    // [N,640]: reps 0..4 as column slices
__device__ float g_agg [(size_t)NN * HID];
__device__ float g_tmp [(size_t)NN * HID];
__device__ float g_invdeg[NN];
__device__ int   g_cnt[NN];
__device__ int   g_cursor[NN];
__device__ int   g_rowptr[NN + 1];
__device__ int   g_col[EE];

// ---------------- CSR build ----------------
__global__ void k_count(const int* __restrict__ dst, int E) {
    int i = blockIdx.x * blockDim.x + threadIdx.x;
    if (i < E) atomicAdd(&g_cnt[dst[i]], 1);
}

// single-block exclusive scan over g_cnt -> g_rowptr, plus inv_deg
__global__ void k_scan(int M) {
    __shared__ int sm[1024];
    __shared__ int carry;
    int t = threadIdx.x;
    if (t == 0) carry = 0;
    __syncthreads();
    for (int base = 0; base < M; base += 1024) {
        int i = base + t;
        int v = (i < M) ? g_cnt[i] : 0;
        if (i < M) g_invdeg[i] = 1.0f / fmaxf((float)v, 1.0f);
        sm[t] = v;
        __syncthreads();
        #pragma unroll
        for (int off = 1; off < 1024; off <<= 1) {
            int add = (t >= off) ? sm[t - off] : 0;
            __syncthreads();
            sm[t] += add;
            __syncthreads();
        }
        int incl = sm[t];
        int c = carry;
        __syncthreads();                 // everyone read carry before update
        if (i < M) g_rowptr[i] = c + incl - v;
        if (t == 1023) carry = c + sm[1023];
        __syncthreads();
    }
    if (t == 0) g_rowptr[M] = carry;
}

__global__ void k_fill(const int* __restrict__ src, const int* __restrict__ dst, int E) {
    int i = blockIdx.x * blockDim.x + threadIdx.x;
    if (i < E) {
        int d = dst[i];
        int pos = atomicAdd(&g_cursor[d], 1);
        g_col[g_rowptr[d] + pos] = src[i];
    }
}

// ---------------- mean aggregation: one warp per node ----------------
__global__ void k_agg(const float* __restrict__ H /* REPS + i*HID, ld=LD */,
                      float* __restrict__ out, int M) {
    int gw   = (blockIdx.x * blockDim.x + threadIdx.x) >> 5;
    int lane = threadIdx.x & 31;
    if (gw >= M) return;
    int beg = g_rowptr[gw], end = g_rowptr[gw + 1];
    float a0 = 0.f, a1 = 0.f, a2 = 0.f, a3 = 0.f;
    for (int base = beg; base < end; base += 32) {
        int idx = (base + lane < end) ? g_col[base + lane] : 0;
        int cnt = min(32, end - base);
        for (int j = 0; j < cnt; j++) {
            int s = __shfl_sync(0xffffffffu, idx, j);
            const float4 v = *reinterpret_cast<const float4*>(
                H + (size_t)s * LD + lane * 4);
            a0 += v.x; a1 += v.y; a2 += v.z; a3 += v.w;
        }
    }
    float w = g_invdeg[gw];
    float4 r;
    r.x = a0 * w; r.y = a1 * w; r.z = a2 * w; r.w = a3 * w;
    *reinterpret_cast<float4*>(out + (size_t)gw * HID + lane * 4) = r;
}

// ---------------- LayerNorm + optional skip + relu, warp per row ----------------
__global__ void k_ln(const float* __restrict__ T /* [M,HID] */,
                     const float* __restrict__ g, const float* __restrict__ b,
                     const float* __restrict__ skip /* REPS slice (ld=LD) or null */,
                     float* __restrict__ out /* REPS slice (ld=LD) */, int M) {
    int row  = (blockIdx.x * blockDim.x + threadIdx.x) >> 5;
    int lane = threadIdx.x & 31;
    if (row >= M) return;
    float4 v = *reinterpret_cast<const float4*>(T + (size_t)row * HID + lane * 4);
    float s  = v.x + v.y + v.z + v.w;
    float ss = v.x * v.x + v.y * v.y + v.z * v.z + v.w * v.w;
    #pragma unroll
    for (int off = 16; off; off >>= 1) {
        s  += __shfl_xor_sync(0xffffffffu, s,  off);
        ss += __shfl_xor_sync(0xffffffffu, ss, off);
    }
    float mu  = s * (1.0f / 128.0f);
    float var = ss * (1.0f / 128.0f) - mu * mu;
    float inv = rsqrtf(var + 1e-5f);
    float4 gg = *reinterpret_cast<const float4*>(g + lane * 4);
    float4 bb = *reinterpret_cast<const float4*>(b + lane * 4);
    float4 o;
    o.x = (v.x - mu) * inv * gg.x + bb.x;
    o.y = (v.y - mu) * inv * gg.y + bb.y;
    o.z = (v.z - mu) * inv * gg.z + bb.z;
    o.w = (v.w - mu) * inv * gg.w + bb.w;
    if (skip) {
        float4 sk = *reinterpret_cast<const float4*>(skip + (size_t)row * LD + lane * 4);
        o.x += sk.x; o.y += sk.y; o.z += sk.z; o.w += sk.w;
    }
    o.x = fmaxf(o.x, 0.f); o.y = fmaxf(o.y, 0.f);
    o.z = fmaxf(o.z, 0.f); o.w = fmaxf(o.w, 0.f);
    *reinterpret_cast<float4*>(out + (size_t)row * LD + lane * 4) = o;
}

// ---------------- SIMT SGEMM: C[M,128] = act(A[M,K] @ W[K,128] + bias (+C)) ----------------
// BM=128, BN=128, BK=16, 256 threads, 8x8 micro-tile.
template <bool RELU, bool ACC>
__global__ void __launch_bounds__(256)
k_gemm(const float* __restrict__ A, int lda,
       const float* __restrict__ W, const float* __restrict__ bias,
       float* __restrict__ C, int ldc, int M, int K) {
    __shared__ float As[16][128];
    __shared__ float Ws[16][128];
    const int tid = threadIdx.x;
    const int m0  = blockIdx.x * 128;
    const int tx  = tid & 15, ty = tid >> 4;

    float acc[8][8];
    #pragma unroll
    for (int i = 0; i < 8; i++)
        #pragma unroll
        for (int j = 0; j < 8; j++) acc[i][j] = 0.f;

    const int lm = tid >> 1;          // A-load row 0..127
    const int lk = (tid & 1) * 8;     // A-load k offset 0/8
    const int wk = tid >> 4;          // W-load row 0..15
    const int wn = (tid & 15) * 8;    // W-load col

    for (int kt = 0; kt < K; kt += 16) {
        {   // A tile (scalar loads, arbitrary lda, zero-fill OOB)
            int row = m0 + lm;
            const float* ap = A + (size_t)row * lda + kt + lk;
            #pragma unroll
            for (int i = 0; i < 8; i++) {
                int kk = kt + lk + i;
                As[lk + i][lm] = (row < M && kk < K) ? ap[i] : 0.f;
            }
        }
        {   // W tile (vectorized, always 128 wide)
            int kk = kt + wk;
            if (kk < K) {
                const float4* wp = reinterpret_cast<const float4*>(W + (size_t)kk * 128 + wn);
                *reinterpret_cast<float4*>(&Ws[wk][wn])     = wp[0];
                *reinterpret_cast<float4*>(&Ws[wk][wn + 4]) = wp[1];
            } else {
                float4 z = {0.f, 0.f, 0.f, 0.f};
                *reinterpret_cast<float4*>(&Ws[wk][wn])     = z;
                *reinterpret_cast<float4*>(&Ws[wk][wn + 4]) = z;
            }
        }
        __syncthreads();
        #pragma unroll
        for (int k = 0; k < 16; k++) {
            float a[8], bv[8];
            *reinterpret_cast<float4*>(a)      = *reinterpret_cast<float4*>(&As[k][ty * 8]);
            *reinterpret_cast<float4*>(a + 4)  = *reinterpret_cast<float4*>(&As[k][ty * 8 + 4]);
            *reinterpret_cast<float4*>(bv)     = *reinterpret_cast<float4*>(&Ws[k][tx * 8]);
            *reinterpret_cast<float4*>(bv + 4) = *reinterpret_cast<float4*>(&Ws[k][tx * 8 + 4]);
            #pragma unroll
            for (int i = 0; i < 8; i++)
                #pragma unroll
                for (int j = 0; j < 8; j++)
                    acc[i][j] += a[i] * bv[j];
        }
        __syncthreads();
    }

    float bv[8];
    if (bias) {
        *reinterpret_cast<float4*>(bv)     = *reinterpret_cast<const float4*>(bias + tx * 8);
        *reinterpret_cast<float4*>(bv + 4) = *reinterpret_cast<const float4*>(bias + tx * 8 + 4);
    } else {
        #pragma unroll
        for (int j = 0; j < 8; j++) bv[j] = 0.f;
    }
    #pragma unroll
    for (int i = 0; i < 8; i++) {
        int row = m0 + ty * 8 + i;
        if (row < M) {
            float* cp = C + (size_t)row * ldc + tx * 8;
            float v[8];
            #pragma unroll
            for (int j = 0; j < 8; j++) v[j] = acc[i][j] + bv[j];
            if (ACC) {
                float4 o0 = *reinterpret_cast<float4*>(cp);
                float4 o1 = *reinterpret_cast<float4*>(cp + 4);
                v[0] += o0.x; v[1] += o0.y; v[2] += o0.z; v[3] += o0.w;
                v[4] += o1.x; v[5] += o1.y; v[6] += o1.z; v[7] += o1.w;
            }
            if (RELU) {
                #pragma unroll
                for (int j = 0; j < 8; j++) v[j] = fmaxf(v[j], 0.f);
            }
            float4 s0 = {v[0], v[1], v[2], v[3]};
            float4 s1 = {v[4], v[5], v[6], v[7]};
            *reinterpret_cast<float4*>(cp)     = s0;
            *reinterpret_cast<float4*>(cp + 4) = s1;
        }
    }
}

// ---------------- launch ----------------
extern "C" void kernel_launch(void* const* d_in, const int* in_sizes, int n_in,
                              void* d_out, int out_size) {
    const float* x       = (const float*)d_in[0];
    const int*   ei      = (const int*)  d_in[1];
    const float* emb_W   = (const float*)d_in[2];
    const float* emb_b   = (const float*)d_in[3];
    const float* lin_l_W = (const float*)d_in[4];
    const float* lin_l_b = (const float*)d_in[5];
    const float* lin_r_W = (const float*)d_in[6];
    const float* ln_g    = (const float*)d_in[7];
    const float* ln_b    = (const float*)d_in[8];
    const float* fus_W1  = (const float*)d_in[9];
    const float* fus_b1  = (const float*)d_in[10];
    const float* fus_W2  = (const float*)d_in[11];
    const float* fus_b2  = (const float*)d_in[12];
    float* out = (float*)d_out;

    const int M = in_sizes[0] / INDIM;   // 50000
    const int E = in_sizes[1] / 2;       // 800000

    float *REPS, *AGG, *TMP;
    int *CNT, *CURSOR;
    cudaGetSymbolAddress((void**)&REPS,   g_REPS);
    cudaGetSymbolAddress((void**)&AGG,    g_agg);
    cudaGetSymbolAddress((void**)&TMP,    g_tmp);
    cudaGetSymbolAddress((void**)&CNT,    g_cnt);
    cudaGetSymbolAddress((void**)&CURSOR, g_cursor);

    const int* src = ei;
    const int* dst = ei + E;

    cudaMemsetAsync(CNT,    0, (size_t)M * sizeof(int), 0);
    cudaMemsetAsync(CURSOR, 0, (size_t)M * sizeof(int), 0);

    // CSR build
    k_count<<<(E + 255) / 256, 256>>>(dst, E);
    k_scan<<<1, 1024>>>(M);
    k_fill<<<(E + 255) / 256, 256>>>(src, dst, E);

    const int gemm_grid = (M + 127) / 128;
    const int warp_grid = (M + 7) / 8;   // 8 warps per 256-thread block

    // embedding: relu(x @ emb_W + emb_b) -> REPS slice 0 (ld=640)
    k_gemm<true, false><<<gemm_grid, 256>>>(x, INDIM, emb_W, emb_b, REPS, LD, M, INDIM);

    for (int i = 0; i < NL; i++) {
        const float* Hi = REPS + i * HID;              // slice i, ld=640
        // mean aggregation
        k_agg<<<warp_grid, 256>>>(Hi, AGG, M);
        // tmp = agg @ lin_l_W[i] + lin_l_b[i]
        k_gemm<false, false><<<gemm_grid, 256>>>(AGG, HID, lin_l_W + i * HID * HID,
                                                 lin_l_b + i * HID, TMP, HID, M, HID);
        // tmp += h @ lin_r_W[i]
        k_gemm<false, true><<<gemm_grid, 256>>>(Hi, LD, lin_r_W + i * HID * HID,
                                                nullptr, TMP, HID, M, HID);
        // LN (+skip for i>0) + relu -> REPS slice i+1
        k_ln<<<warp_grid, 256>>>(TMP, ln_g + i * HID, ln_b + i * HID,
                                 (i > 0) ? Hi : nullptr,
                                 REPS + (i + 1) * HID, M);
    }

    // fusion MLP: tmp = relu(REPS @ fus_W1 + fus_b1); out = tmp @ fus_W2 + fus_b2
    k_gemm<true, false><<<gemm_grid, 256>>>(REPS, LD, fus_W1, fus_b1, TMP, HID, M, LD);
    k_gemm<false, false><<<gemm_grid, 256>>>(TMP, HID, fus_W2, fus_b2, out, HID, M, HID);
}

// round 3
// speedup vs baseline: 1.6932x; 1.6932x over previous
#include <cuda_runtime.h>
#include <cuda_bf16.h>
#include <cstdint>
#include <math.h>

#define NN    50000
#define EE    800000
#define INDIM 300
#define HID   128
#define NL    4
#define LD    640        // (NL+1)*HID fp32 reps row
#define LD3   1920       // 3*LD  split-bf16 reps row
#define K3_X  960        // padded 3*300 (300->320 triples)
#define K3_H  384        // 3*128
#define K3_F  1920       // 3*640

// weight pack offsets (elements)
#define OFF_EMBW 0
#define OFF_LINL 122880
#define OFF_LINR 319488
#define OFF_FUS1 516096
#define OFF_FUS2 761856
#define W3_TOTAL 811008

// dynamic smem: 1024 align slack + max(tiles 64KB, C 128*132*4=67584)
#define DSMEM (1024 + 67584)

// ---------------- scratch (device globals) ----------------
__device__ __align__(256) float          g_REPS [(size_t)NN * LD];
__device__ __align__(256) __nv_bfloat16  g_REPS3[(size_t)NN * LD3];
__device__ __align__(256) __nv_bfloat16  g_X3   [(size_t)NN * K3_X];
__device__ __align__(256) __nv_bfloat16  g_AGG3 [(size_t)NN * K3_H];
__device__ __align__(256) __nv_bfloat16  g_TMP3 [(size_t)NN * K3_H];
__device__ __align__(256) __nv_bfloat16  g_W3   [W3_TOTAL];
__device__ float g_invdeg[NN];
__device__ int   g_cnt[NN];
__device__ int   g_cursor[NN];
__device__ int   g_rowptr[NN + 1];
__device__ int   g_col[EE];

// ---------------- helpers ----------------
__device__ __forceinline__ uint32_t smem_u32(const void* p) {
    uint32_t a;
    asm("{ .reg .u64 t; cvta.to.shared.u64 t, %1; cvt.u32.u64 %0, t; }" : "=r"(a) : "l"(p));
    return a;
}
#define SW128(b) ((b) ^ (((b) >> 3) & 0x70))

__device__ __forceinline__ void cp16(uint32_t dst, const void* src, int sz) {
    asm volatile("cp.async.cg.shared.global [%0], [%1], 16, %2;"
                 :: "r"(dst), "l"(src), "r"(sz) : "memory");
}
__device__ __forceinline__ void ldm_x4(uint32_t* r, uint32_t addr) {
    asm volatile("ldmatrix.sync.aligned.m8n8.x4.shared.b16 {%0,%1,%2,%3}, [%4];"
                 : "=r"(r[0]), "=r"(r[1]), "=r"(r[2]), "=r"(r[3]) : "r"(addr));
}
__device__ __forceinline__ void ldm_x2(uint32_t* r, uint32_t addr) {
    asm volatile("ldmatrix.sync.aligned.m8n8.x2.shared.b16 {%0,%1}, [%2];"
                 : "=r"(r[0]), "=r"(r[1]) : "r"(addr));
}
__device__ __forceinline__ void mma_bf16(float* c, const uint32_t* a, const uint32_t* b) {
    asm volatile(
        "mma.sync.aligned.m16n8k16.row.col.f32.bf16.bf16.f32 "
        "{%0,%1,%2,%3}, {%4,%5,%6,%7}, {%8,%9}, {%0,%1,%2,%3};"
        : "+f"(c[0]), "+f"(c[1]), "+f"(c[2]), "+f"(c[3])
        : "r"(a[0]), "r"(a[1]), "r"(a[2]), "r"(a[3]), "r"(b[0]), "r"(b[1]));
}
__device__ __forceinline__ void split2(float v, __nv_bfloat16& hi, __nv_bfloat16& lo) {
    hi = __float2bfloat16(v);
    lo = __float2bfloat16(v - __bfloat162float(hi));
}

// ---------------- CSR build ----------------
__global__ void k_count(const int* __restrict__ dst, int E) {
    int i = blockIdx.x * blockDim.x + threadIdx.x;
    if (i < E) atomicAdd(&g_cnt[dst[i]], 1);
}
__global__ void k_scan(int M) {
    __shared__ int sm[1024];
    __shared__ int carry;
    int t = threadIdx.x;
    if (t == 0) carry = 0;
    __syncthreads();
    for (int base = 0; base < M; base += 1024) {
        int i = base + t;
        int v = (i < M) ? g_cnt[i] : 0;
        if (i < M) g_invdeg[i] = 1.0f / fmaxf((float)v, 1.0f);
        sm[t] = v;
        __syncthreads();
        #pragma unroll
        for (int off = 1; off < 1024; off <<= 1) {
            int add = (t >= off) ? sm[t - off] : 0;
            __syncthreads();
            sm[t] += add;
            __syncthreads();
        }
        int incl = sm[t];
        int c = carry;
        __syncthreads();
        if (i < M) g_rowptr[i] = c + incl - v;
        if (t == 1023) carry = c + sm[1023];
        __syncthreads();
    }
    if (t == 0) g_rowptr[M] = carry;
}
__global__ void k_fill(const int* __restrict__ src, const int* __restrict__ dst, int E) {
    int i = blockIdx.x * blockDim.x + threadIdx.x;
    if (i < E) {
        int d = dst[i];
        int pos = atomicAdd(&g_cursor[d], 1);
        g_col[g_rowptr[d] + pos] = src[i];
    }
}

// ---------------- conversions ----------------
// weights: W [K,128] fp32 -> out [128, 3*Kp] bf16, B-pattern [hi,lo,hi], transpose
__global__ void k_wsplit(const float* __restrict__ W, int K, int Kp,
                         __nv_bfloat16* __restrict__ out) {
    int idx = blockIdx.x * blockDim.x + threadIdx.x;
    if (idx >= 128 * Kp) return;
    int n = idx / Kp, kp = idx % Kp;
    __nv_bfloat16 hi, lo;
    if (kp < K) {
        split2(W[(size_t)kp * 128 + n], hi, lo);
    } else {
        hi = __float2bfloat16(0.f); lo = hi;
    }
    __nv_bfloat16* o = out + (size_t)n * (3 * Kp) + 3 * kp;
    o[0] = hi; o[1] = lo; o[2] = hi;
}

// x [M,300] fp32 -> X3 [M,960] bf16, A-pattern [hi,hi,lo], zero pad
__global__ void k_xsplit(const float* __restrict__ x, __nv_bfloat16* __restrict__ out, int M) {
    int idx = blockIdx.x * blockDim.x + threadIdx.x;
    int row = idx / 80, g = idx % 80;
    if (row >= M) return;
    float vv[4] = {0.f, 0.f, 0.f, 0.f};
    if (g < 75) {
        float4 t = *reinterpret_cast<const float4*>(x + (size_t)row * INDIM + g * 4);
        vv[0] = t.x; vv[1] = t.y; vv[2] = t.z; vv[3] = t.w;
    }
    union { __nv_bfloat16 h[12]; uint2 u[3]; } p;
    #pragma unroll
    for (int j = 0; j < 4; j++) {
        __nv_bfloat16 hi, lo; split2(vv[j], hi, lo);
        p.h[3 * j] = hi; p.h[3 * j + 1] = hi; p.h[3 * j + 2] = lo;
    }
    uint2* d = reinterpret_cast<uint2*>(out + (size_t)row * K3_X + g * 12);
    d[0] = p.u[0]; d[1] = p.u[1]; d[2] = p.u[2];
}

// ---------------- mean aggregation -> split bf16 directly ----------------
__global__ void k_agg(const float* __restrict__ H /* REPS slice, ld=LD */,
                      __nv_bfloat16* __restrict__ out3, int M) {
    int gw   = (blockIdx.x * blockDim.x + threadIdx.x) >> 5;
    int lane = threadIdx.x & 31;
    if (gw >= M) return;
    int beg = g_rowptr[gw], end = g_rowptr[gw + 1];
    float a0 = 0.f, a1 = 0.f, a2 = 0.f, a3 = 0.f;
    for (int base = beg; base < end; base += 32) {
        int idx = (base + lane < end) ? g_col[base + lane] : 0;
        int cnt = min(32, end - base);
        for (int j = 0; j < cnt; j++) {
            int s = __shfl_sync(0xffffffffu, idx, j);
            const float4 v = *reinterpret_cast<const float4*>(H + (size_t)s * LD + lane * 4);
            a0 += v.x; a1 += v.y; a2 += v.z; a3 += v.w;
        }
    }
    float w = g_invdeg[gw];
    float m[4] = {a0 * w, a1 * w, a2 * w, a3 * w};
    union { __nv_bfloat16 h[12]; uint2 u[3]; } p;
    #pragma unroll
    for (int j = 0; j < 4; j++) {
        __nv_bfloat16 hi, lo; split2(m[j], hi, lo);
        p.h[3 * j] = hi; p.h[3 * j + 1] = hi; p.h[3 * j + 2] = lo;
    }
    uint2* d = reinterpret_cast<uint2*>(out3 + (size_t)gw * K3_H + lane * 12);
    d[0] = p.u[0]; d[1] = p.u[1]; d[2] = p.u[2];
}

// ---------------- tile loader (cp.async, SW128 swizzle) ----------------
__device__ __forceinline__ void load_tiles(uint32_t tiles, int s, int tid, int m0, int M,
                                           const __nv_bfloat16* A, int lda,
                                           const __nv_bfloat16* B, int K, int k0) {
    uint32_t abase = tiles + (uint32_t)s * 32768u;
    uint32_t bbase = abase + 16384u;
    #pragma unroll
    for (int i = 0; i < 4; i++) {
        int v = tid + i * 256;
        int r = v >> 3, ch = v & 7;
        uint32_t bo = (uint32_t)(r * 128 + ch * 16);
        int row = m0 + r;
        int rc = row < M ? row : 0;
        const __nv_bfloat16* src = A + (size_t)rc * lda + k0 + ch * 8;
        cp16(abase + SW128(bo), src, row < M ? 16 : 0);
    }
    #pragma unroll
    for (int i = 0; i < 4; i++) {
        int v = tid + i * 256;
        int r = v >> 3, ch = v & 7;
        uint32_t bo = (uint32_t)(r * 128 + ch * 16);
        cp16(bbase + SW128(bo), B + (size_t)r * K + k0 + ch * 8, 16);
    }
    asm volatile("cp.async.commit_group;" ::: "memory");
}

// ---------------- mma.sync GEMM, 128x128 tile, BK=64, dual-segment ----------------
// MODE 0: out = acc + bias                      -> outF (ldF)
// MODE 1: v = relu(acc+bias)                    -> outF (opt) + split out3
// MODE 2: v = LN(acc+bias)*g+b (+skip), relu    -> outF + split out3
template <int MODE>
__global__ void __launch_bounds__(256)
k_mgemm(const __nv_bfloat16* __restrict__ A0, int lda0, const __nv_bfloat16* __restrict__ B0, int K0,
        const __nv_bfloat16* __restrict__ A1, int lda1, const __nv_bfloat16* __restrict__ B1, int K1,
        const float* __restrict__ bias, const float* __restrict__ lng, const float* __restrict__ lnb,
        const float* __restrict__ skip, float* __restrict__ outF, int ldF,
        __nv_bfloat16* __restrict__ out3, int ld3, int M) {
    extern __shared__ char smem_raw[];
    char* smem = (char*)(((uintptr_t)smem_raw + 1023) & ~(uintptr_t)1023);
    const uint32_t tiles = smem_u32(smem);

    const int tid  = threadIdx.x;
    const int lane = tid & 31, wid = tid >> 5;
    const int m0   = blockIdx.x * 128;

    const int wm = (wid & 1) * 64;      // warp m offset (64-row half)
    const int wn = (wid >> 1) * 32;     // warp n offset (32-col quarter)

    float acc[4][4][4];
    #pragma unroll
    for (int i = 0; i < 4; i++)
        #pragma unroll
        for (int j = 0; j < 4; j++)
            #pragma unroll
            for (int q = 0; q < 4; q++) acc[i][j][q] = 0.f;

    const int nk0 = K0 / 64;
    const int nk  = nk0 + K1 / 64;

    // ldmatrix lane address components
    const int r_in = ((lane >> 3) & 1) * 8 + (lane & 7);
    const int ca8  = (lane >> 4) * 8;
    const int rb   = lane & 7;
    const int cb8  = ((lane >> 3) & 1) * 8;

    load_tiles(tiles, 0, tid, m0, M, A0, lda0, B0, K0, 0);

    #pragma unroll 1
    for (int c = 0; c < nk; c++) {
        if (c + 1 < nk) {
            int cn = c + 1;
            if (cn < nk0) load_tiles(tiles, cn & 1, tid, m0, M, A0, lda0, B0, K0, cn * 64);
            else          load_tiles(tiles, cn & 1, tid, m0, M, A1, lda1, B1, K1, (cn - nk0) * 64);
            asm volatile("cp.async.wait_group 1;" ::: "memory");
        } else {
            asm volatile("cp.async.wait_group 0;" ::: "memory");
        }
        __syncthreads();

        uint32_t abase = tiles + (uint32_t)(c & 1) * 32768u;
        uint32_t bbase = abase + 16384u;
        #pragma unroll
        for (int ka = 0; ka < 4; ka++) {
            uint32_t a[4][4];
            #pragma unroll
            for (int ma = 0; ma < 4; ma++) {
                int r = wm + ma * 16 + r_in, cc = ka * 16 + ca8;
                ldm_x4(a[ma], abase + SW128((uint32_t)(r * 128 + cc * 2)));
            }
            uint32_t b[4][2];
            #pragma unroll
            for (int na = 0; na < 4; na++) {
                int r = wn + na * 8 + rb, cc = ka * 16 + cb8;
                ldm_x2(b[na], bbase + SW128((uint32_t)(r * 128 + cc * 2)));
            }
            #pragma unroll
            for (int ma = 0; ma < 4; ma++)
                #pragma unroll
                for (int na = 0; na < 4; na++)
                    mma_bf16(acc[ma][na], a[ma], b[na]);
        }
        __syncthreads();
    }

    // ---- park accumulators in smem C [128][132] fp32 (reuses tile smem) ----
    float* C = (float*)smem;
    #pragma unroll
    for (int ma = 0; ma < 4; ma++)
        #pragma unroll
        for (int na = 0; na < 4; na++) {
            int r0 = wm + ma * 16 + (lane >> 2);
            int cc = wn + na * 8 + 2 * (lane & 3);
            C[r0 * 132 + cc]           = acc[ma][na][0];
            C[r0 * 132 + cc + 1]       = acc[ma][na][1];
            C[(r0 + 8) * 132 + cc]     = acc[ma][na][2];
            C[(r0 + 8) * 132 + cc + 1] = acc[ma][na][3];
        }
    __syncthreads();

    // ---- epilogue: warp per row (16 rows per warp), lane owns 4 cols ----
    #pragma unroll 1
    for (int t = 0; t < 16; t++) {
        int rr  = wid + t * 8;
        int row = m0 + rr;
        if (row >= M) continue;
        float4 v = *reinterpret_cast<float4*>(C + rr * 132 + lane * 4);
        float4 bb = *reinterpret_cast<const float4*>(bias + lane * 4);
        v.x += bb.x; v.y += bb.y; v.z += bb.z; v.w += bb.w;
        if (MODE == 2) {
            float s  = v.x + v.y + v.z + v.w;
            float ss = v.x * v.x + v.y * v.y + v.z * v.z + v.w * v.w;
            #pragma unroll
            for (int off = 16; off; off >>= 1) {
                s  += __shfl_xor_sync(0xffffffffu, s,  off);
                ss += __shfl_xor_sync(0xffffffffu, ss, off);
            }
            float mu  = s * (1.0f / 128.0f);
            float var = ss * (1.0f / 128.0f) - mu * mu;
            float inv = rsqrtf(var + 1e-5f);
            float4 gg = *reinterpret_cast<const float4*>(lng + lane * 4);
            float4 ob = *reinterpret_cast<const float4*>(lnb + lane * 4);
            v.x = (v.x - mu) * inv * gg.x + ob.x;
            v.y = (v.y - mu) * inv * gg.y + ob.y;
            v.z = (v.z - mu) * inv * gg.z + ob.z;
            v.w = (v.w - mu) * inv * gg.w + ob.w;
            if (skip) {
                float4 sk = *reinterpret_cast<const float4*>(skip + (size_t)row * LD + lane * 4);
                v.x += sk.x; v.y += sk.y; v.z += sk.z; v.w += sk.w;
            }
        }
        if (MODE != 0) {
            v.x = fmaxf(v.x, 0.f); v.y = fmaxf(v.y, 0.f);
            v.z = fmaxf(v.z, 0.f); v.w = fmaxf(v.w, 0.f);
        }
        if (MODE == 0 || MODE == 2 || outF != nullptr) {
            *reinterpret_cast<float4*>(outF + (size_t)row * ldF + lane * 4) = v;
        }
        if (MODE != 0) {
            union { __nv_bfloat16 h[12]; uint2 u[3]; } p;
            float vv[4] = {v.x, v.y, v.z, v.w};
            #pragma unroll
            for (int jj = 0; jj < 4; jj++) {
                __nv_bfloat16 hi, lo; split2(vv[jj], hi, lo);
                p.h[3 * jj] = hi; p.h[3 * jj + 1] = hi; p.h[3 * jj + 2] = lo;
            }
            uint2* d = reinterpret_cast<uint2*>(out3 + (size_t)row * ld3 + lane * 12);
            d[0] = p.u[0]; d[1] = p.u[1]; d[2] = p.u[2];
        }
    }
}

// ---------------- launch ----------------
extern "C" void kernel_launch(void* const* d_in, const int* in_sizes, int n_in,
                              void* d_out, int out_size) {
    const float* x       = (const float*)d_in[0];
    const int*   ei      = (const int*)  d_in[1];
    const float* emb_W   = (const float*)d_in[2];
    const float* emb_b   = (const float*)d_in[3];
    const float* lin_l_W = (const float*)d_in[4];
    const float* lin_l_b = (const float*)d_in[5];
    const float* lin_r_W = (const float*)d_in[6];
    const float* ln_g    = (const float*)d_in[7];
    const float* ln_b    = (const float*)d_in[8];
    const float* fus_W1  = (const float*)d_in[9];
    const float* fus_b1  = (const float*)d_in[10];
    const float* fus_W2  = (const float*)d_in[11];
    const float* fus_b2  = (const float*)d_in[12];
    float* out = (float*)d_out;

    const int M = in_sizes[0] / INDIM;
    const int E = in_sizes[1] / 2;

    float *REPS; __nv_bfloat16 *REPS3, *X3, *AGG3, *TMP3, *W3;
    int *CNT, *CURSOR;
    cudaGetSymbolAddress((void**)&REPS,   g_REPS);
    cudaGetSymbolAddress((void**)&REPS3,  g_REPS3);
    cudaGetSymbolAddress((void**)&X3,     g_X3);
    cudaGetSymbolAddress((void**)&AGG3,   g_AGG3);
    cudaGetSymbolAddress((void**)&TMP3,   g_TMP3);
    cudaGetSymbolAddress((void**)&W3,     g_W3);
    cudaGetSymbolAddress((void**)&CNT,    g_cnt);
    cudaGetSymbolAddress((void**)&CURSOR, g_cursor);

    cudaFuncSetAttribute(k_mgemm<0>, cudaFuncAttributeMaxDynamicSharedMemorySize, DSMEM);
    cudaFuncSetAttribute(k_mgemm<1>, cudaFuncAttributeMaxDynamicSharedMemorySize, DSMEM);
    cudaFuncSetAttribute(k_mgemm<2>, cudaFuncAttributeMaxDynamicSharedMemorySize, DSMEM);

    const int* src = ei;
    const int* dst = ei + E;

    cudaMemsetAsync(CNT,    0, (size_t)M * sizeof(int), 0);
    cudaMemsetAsync(CURSOR, 0, (size_t)M * sizeof(int), 0);

    // CSR build
    k_count<<<(E + 255) / 256, 256>>>(dst, E);
    k_scan<<<1, 1024>>>(M);
    k_fill<<<(E + 255) / 256, 256>>>(src, dst, E);

    // weight prep (transpose + split)
    k_wsplit<<<(128 * 320 + 255) / 256, 256>>>(emb_W, 300, 320, W3 + OFF_EMBW);
    for (int i = 0; i < NL; i++) {
        k_wsplit<<<(128 * 128 + 255) / 256, 256>>>(lin_l_W + (size_t)i * HID * HID, 128, 128,
                                                   W3 + OFF_LINL + (size_t)i * 49152);
        k_wsplit<<<(128 * 128 + 255) / 256, 256>>>(lin_r_W + (size_t)i * HID * HID, 128, 128,
                                                   W3 + OFF_LINR + (size_t)i * 49152);
    }
    k_wsplit<<<(128 * 640 + 255) / 256, 256>>>(fus_W1, 640, 640, W3 + OFF_FUS1);
    k_wsplit<<<(128 * 128 + 255) / 256, 256>>>(fus_W2, 128, 128, W3 + OFF_FUS2);

    // x -> split
    k_xsplit<<<((M * 80) + 255) / 256, 256>>>(x, X3, M);

    const int G = (M + 127) / 128;
    const int warp_grid = (M + 7) / 8;

    // embedding: relu(x@W+b) -> REPS slice0 fp32 + REPS3 slice0 split
    k_mgemm<1><<<G, 256, DSMEM>>>(X3, K3_X, W3 + OFF_EMBW, K3_X,
                                  nullptr, 0, nullptr, 0,
                                  emb_b, nullptr, nullptr, nullptr,
                                  REPS, LD, REPS3, LD3, M);

    for (int i = 0; i < NL; i++) {
        k_agg<<<warp_grid, 256>>>(REPS + (size_t)i * HID, AGG3, M);
        k_mgemm<2><<<G, 256, DSMEM>>>(AGG3, K3_H, W3 + OFF_LINL + (size_t)i * 49152, K3_H,
                                      REPS3 + (size_t)i * K3_H, LD3,
                                      W3 + OFF_LINR + (size_t)i * 49152, K3_H,
                                      lin_l_b + (size_t)i * HID,
                                      ln_g + (size_t)i * HID, ln_b + (size_t)i * HID,
                                      (i > 0) ? (REPS + (size_t)i * HID) : nullptr,
                                      REPS + (size_t)(i + 1) * HID, LD,
                                      REPS3 + (size_t)(i + 1) * K3_H, LD3, M);
    }

    // fusion MLP
    k_mgemm<1><<<G, 256, DSMEM>>>(REPS3, LD3, W3 + OFF_FUS1, K3_F,
                                  nullptr, 0, nullptr, 0,
                                  fus_b1, nullptr, nullptr, nullptr,
                                  nullptr, 0, TMP3, K3_H, M);
    k_mgemm<0><<<G, 256, DSMEM>>>(TMP3, K3_H, W3 + OFF_FUS2, K3_H,
                                  nullptr, 0, nullptr, 0,
                                  fus_b2, nullptr, nullptr, nullptr,
                                  out, HID, nullptr, 0, M);
}

// round 4
// speedup vs baseline: 1.8504x; 1.0928x over previous
#include <cuda_runtime.h>
#include <cuda_bf16.h>
#include <cstdint>
#include <math.h>

#define NN    50000
#define EE    800000
#define INDIM 300
#define HID   128
#define NL    4
#define LD    640        // (NL+1)*HID fp32 reps row
#define LD3   1920       // 3*LD  split-bf16 reps row
#define K3_X  960        // padded 3*300 (300->320 triples)
#define K3_H  384        // 3*128
#define K3_F  1920       // 3*640

// weight pack offsets (elements)
#define OFF_EMBW 0
#define OFF_LINL 122880
#define OFF_LINR 319488
#define OFF_FUS1 516096
#define OFF_FUS2 761856
#define W3_TOTAL 811008

// dynamic smem: 1024 align slack + max(3 tile stages 96KB, C 128*132*4=67584)
#define DSMEM (1024 + 98304)

// ---------------- scratch (device globals) ----------------
__device__ __align__(256) float          g_REPS [(size_t)NN * LD];
__device__ __align__(256) __nv_bfloat16  g_REPS3[(size_t)NN * LD3];
__device__ __align__(256) __nv_bfloat16  g_X3   [(size_t)NN * K3_X];
__device__ __align__(256) __nv_bfloat16  g_AGG3 [(size_t)NN * K3_H];
__device__ __align__(256) __nv_bfloat16  g_TMP3 [(size_t)NN * K3_H];
__device__ __align__(256) __nv_bfloat16  g_W3   [W3_TOTAL];
__device__ float g_invdeg[NN];
__device__ int   g_cnt[NN];
__device__ int   g_cursor[NN];     // running fill cursor (initialized to rowptr by scan)
__device__ int   g_rowptr[NN + 1];
__device__ int   g_col[EE];

// ---------------- helpers ----------------
__device__ __forceinline__ uint32_t smem_u32(const void* p) {
    uint32_t a;
    asm("{ .reg .u64 t; cvta.to.shared.u64 t, %1; cvt.u32.u64 %0, t; }" : "=r"(a) : "l"(p));
    return a;
}
#define SW128(b) ((b) ^ (((b) >> 3) & 0x70))

__device__ __forceinline__ void cp16(uint32_t dst, const void* src, int sz) {
    asm volatile("cp.async.cg.shared.global [%0], [%1], 16, %2;"
                 :: "r"(dst), "l"(src), "r"(sz) : "memory");
}
__device__ __forceinline__ void ldm_x4(uint32_t* r, uint32_t addr) {
    asm volatile("ldmatrix.sync.aligned.m8n8.x4.shared.b16 {%0,%1,%2,%3}, [%4];"
                 : "=r"(r[0]), "=r"(r[1]), "=r"(r[2]), "=r"(r[3]) : "r"(addr));
}
__device__ __forceinline__ void ldm_x2(uint32_t* r, uint32_t addr) {
    asm volatile("ldmatrix.sync.aligned.m8n8.x2.shared.b16 {%0,%1}, [%2];"
                 : "=r"(r[0]), "=r"(r[1]) : "r"(addr));
}
__device__ __forceinline__ void mma_bf16(float* c, const uint32_t* a, const uint32_t* b) {
    asm volatile(
        "mma.sync.aligned.m16n8k16.row.col.f32.bf16.bf16.f32 "
        "{%0,%1,%2,%3}, {%4,%5,%6,%7}, {%8,%9}, {%0,%1,%2,%3};"
        : "+f"(c[0]), "+f"(c[1]), "+f"(c[2]), "+f"(c[3])
        : "r"(a[0]), "r"(a[1]), "r"(a[2]), "r"(a[3]), "r"(b[0]), "r"(b[1]));
}
__device__ __forceinline__ void split2(float v, __nv_bfloat16& hi, __nv_bfloat16& lo) {
    hi = __float2bfloat16(v);
    lo = __float2bfloat16(v - __bfloat162float(hi));
}

// ---------------- CSR build ----------------
__global__ void k_count(const int* __restrict__ dst, int E) {
    int i = blockIdx.x * blockDim.x + threadIdx.x;
    if (i < E) atomicAdd(&g_cnt[dst[i]], 1);
}

// warp-shuffle block scan: thread t owns strip [t*per, t*per+per)
__global__ void __launch_bounds__(1024) k_scan(int M) {
    const int T = 1024;
    int t = threadIdx.x;
    int per = (M + T - 1) / T;
    int beg = t * per;
    int end = min(beg + per, M);
    int sum = 0;
    for (int i = beg; i < end; i++) sum += g_cnt[i];

    int lane = t & 31, wid = t >> 5;
    int v = sum;
    #pragma unroll
    for (int o = 1; o < 32; o <<= 1) {
        int u = __shfl_up_sync(0xffffffffu, v, o);
        if (lane >= o) v += u;
    }
    __shared__ int ws[32];
    if (lane == 31) ws[wid] = v;
    __syncthreads();
    if (wid == 0) {
        int wv = ws[lane];
        #pragma unroll
        for (int o = 1; o < 32; o <<= 1) {
            int u = __shfl_up_sync(0xffffffffu, wv, o);
            if (lane >= o) wv += u;
        }
        ws[lane] = wv;
    }
    __syncthreads();
    int run = v - sum + (wid ? ws[wid - 1] : 0);   // exclusive prefix of this strip
    for (int i = beg; i < end; i++) {
        int c = g_cnt[i];
        g_rowptr[i] = run;
        g_cursor[i] = run;
        g_invdeg[i] = 1.0f / fmaxf((float)c, 1.0f);
        run += c;
    }
    if (t == T - 1) g_rowptr[M] = run;
}

__global__ void k_fill(const int* __restrict__ src, const int* __restrict__ dst, int E) {
    int i = blockIdx.x * blockDim.x + threadIdx.x;
    if (i < E) {
        int pos = atomicAdd(&g_cursor[dst[i]], 1);
        g_col[pos] = src[i];
    }
}

// ---------------- weight prep: all weights in ONE launch ----------------
// per element: W [K,128] fp32 -> out [128, 3*Kp] bf16, B-pattern [hi,lo,hi], transpose
__device__ __forceinline__ void wsplit_one(const float* W, __nv_bfloat16* o3,
                                           int idx, int K, int Kp) {
    int n = idx / Kp, kp = idx % Kp;
    __nv_bfloat16 hi, lo;
    if (kp < K) {
        split2(W[(size_t)kp * 128 + n], hi, lo);
    } else {
        hi = __float2bfloat16(0.f); lo = hi;
    }
    __nv_bfloat16* o = o3 + (size_t)n * (3 * Kp) + 3 * kp;
    o[0] = hi; o[1] = lo; o[2] = hi;
}

__global__ void k_wsplit_all(const float* __restrict__ emb_W,
                             const float* __restrict__ lin_l_W,
                             const float* __restrict__ lin_r_W,
                             const float* __restrict__ fus_W1,
                             const float* __restrict__ fus_W2) {
    int w = blockIdx.x * blockDim.x + threadIdx.x;
    if (w < 40960) {
        wsplit_one(emb_W, g_W3 + OFF_EMBW, w, 300, 320);
    } else if (w < 106496) {
        int u = w - 40960, i = u >> 14;
        wsplit_one(lin_l_W + (size_t)i * 16384, g_W3 + OFF_LINL + (size_t)i * 49152,
                   u & 16383, 128, 128);
    } else if (w < 172032) {
        int u = w - 106496, i = u >> 14;
        wsplit_one(lin_r_W + (size_t)i * 16384, g_W3 + OFF_LINR + (size_t)i * 49152,
                   u & 16383, 128, 128);
    } else if (w < 253952) {
        wsplit_one(fus_W1, g_W3 + OFF_FUS1, w - 172032, 640, 640);
    } else if (w < 270336) {
        wsplit_one(fus_W2, g_W3 + OFF_FUS2, w - 253952, 128, 128);
    }
}

// x [M,300] fp32 -> X3 [M,960] bf16, A-pattern [hi,hi,lo], zero pad
__global__ void k_xsplit(const float* __restrict__ x, __nv_bfloat16* __restrict__ out, int M) {
    int idx = blockIdx.x * blockDim.x + threadIdx.x;
    int row = idx / 80, g = idx % 80;
    if (row >= M) return;
    float vv[4] = {0.f, 0.f, 0.f, 0.f};
    if (g < 75) {
        float4 t = *reinterpret_cast<const float4*>(x + (size_t)row * INDIM + g * 4);
        vv[0] = t.x; vv[1] = t.y; vv[2] = t.z; vv[3] = t.w;
    }
    union { __nv_bfloat16 h[12]; uint2 u[3]; } p;
    #pragma unroll
    for (int j = 0; j < 4; j++) {
        __nv_bfloat16 hi, lo; split2(vv[j], hi, lo);
        p.h[3 * j] = hi; p.h[3 * j + 1] = hi; p.h[3 * j + 2] = lo;
    }
    uint2* d = reinterpret_cast<uint2*>(out + (size_t)row * K3_X + g * 12);
    d[0] = p.u[0]; d[1] = p.u[1]; d[2] = p.u[2];
}

// ---------------- mean aggregation -> split bf16 directly ----------------
__global__ void k_agg(const float* __restrict__ H /* REPS slice, ld=LD */,
                      __nv_bfloat16* __restrict__ out3, int M) {
    int gw   = (blockIdx.x * blockDim.x + threadIdx.x) >> 5;
    int lane = threadIdx.x & 31;
    if (gw >= M) return;
    int beg = g_rowptr[gw], end = g_rowptr[gw + 1];
    float a0 = 0.f, a1 = 0.f, a2 = 0.f, a3 = 0.f;
    float b0 = 0.f, b1 = 0.f, b2 = 0.f, b3 = 0.f;
    for (int base = beg; base < end; base += 32) {
        int idx = (base + lane < end) ? g_col[base + lane] : 0;
        int cnt = min(32, end - base);
        int j = 0;
        for (; j + 3 < cnt; j += 4) {
            int s0 = __shfl_sync(0xffffffffu, idx, j);
            int s1 = __shfl_sync(0xffffffffu, idx, j + 1);
            int s2 = __shfl_sync(0xffffffffu, idx, j + 2);
            int s3 = __shfl_sync(0xffffffffu, idx, j + 3);
            float4 v0 = *reinterpret_cast<const float4*>(H + (size_t)s0 * LD + lane * 4);
            float4 v1 = *reinterpret_cast<const float4*>(H + (size_t)s1 * LD + lane * 4);
            float4 v2 = *reinterpret_cast<const float4*>(H + (size_t)s2 * LD + lane * 4);
            float4 v3 = *reinterpret_cast<const float4*>(H + (size_t)s3 * LD + lane * 4);
            a0 += v0.x; a1 += v0.y; a2 += v0.z; a3 += v0.w;
            b0 += v1.x; b1 += v1.y; b2 += v1.z; b3 += v1.w;
            a0 += v2.x; a1 += v2.y; a2 += v2.z; a3 += v2.w;
            b0 += v3.x; b1 += v3.y; b2 += v3.z; b3 += v3.w;
        }
        for (; j < cnt; j++) {
            int s = __shfl_sync(0xffffffffu, idx, j);
            float4 v = *reinterpret_cast<const float4*>(H + (size_t)s * LD + lane * 4);
            a0 += v.x; a1 += v.y; a2 += v.z; a3 += v.w;
        }
    }
    a0 += b0; a1 += b1; a2 += b2; a3 += b3;
    float w = g_invdeg[gw];
    float m[4] = {a0 * w, a1 * w, a2 * w, a3 * w};
    union { __nv_bfloat16 h[12]; uint2 u[3]; } p;
    #pragma unroll
    for (int j = 0; j < 4; j++) {
        __nv_bfloat16 hi, lo; split2(m[j], hi, lo);
        p.h[3 * j] = hi; p.h[3 * j + 1] = hi; p.h[3 * j + 2] = lo;
    }
    uint2* d = reinterpret_cast<uint2*>(out3 + (size_t)gw * K3_H + lane * 12);
    d[0] = p.u[0]; d[1] = p.u[1]; d[2] = p.u[2];
}

// ---------------- tile loader (cp.async, SW128 swizzle) ----------------
__device__ __forceinline__ void load_tiles(uint32_t tiles, int s, int tid, int m0, int M,
                                           const __nv_bfloat16* A, int lda,
                                           const __nv_bfloat16* B, int K, int k0) {
    uint32_t abase = tiles + (uint32_t)s * 32768u;
    uint32_t bbase = abase + 16384u;
    #pragma unroll
    for (int i = 0; i < 4; i++) {
        int v = tid + i * 256;
        int r = v >> 3, ch = v & 7;
        uint32_t bo = (uint32_t)(r * 128 + ch * 16);
        int row = m0 + r;
        int rc = row < M ? row : 0;
        const __nv_bfloat16* src = A + (size_t)rc * lda + k0 + ch * 8;
        cp16(abase + SW128(bo), src, row < M ? 16 : 0);
    }
    #pragma unroll
    for (int i = 0; i < 4; i++) {
        int v = tid + i * 256;
        int r = v >> 3, ch = v & 7;
        uint32_t bo = (uint32_t)(r * 128 + ch * 16);
        cp16(bbase + SW128(bo), B + (size_t)r * K + k0 + ch * 8, 16);
    }
    asm volatile("cp.async.commit_group;" ::: "memory");
}

// ---------------- mma.sync GEMM, 128x128 tile, BK=64, 3-stage, dual-segment ----------------
// MODE 0: out = acc + bias                      -> outF (ldF)
// MODE 1: v = relu(acc+bias)                    -> outF (opt) + split out3
// MODE 2: v = LN(acc+bias)*g+b (+skip), relu    -> outF + split out3
template <int MODE>
__global__ void __launch_bounds__(256)
k_mgemm(const __nv_bfloat16* __restrict__ A0, int lda0, const __nv_bfloat16* __restrict__ B0, int K0,
        const __nv_bfloat16* __restrict__ A1, int lda1, const __nv_bfloat16* __restrict__ B1, int K1,
        const float* __restrict__ bias, const float* __restrict__ lng, const float* __restrict__ lnb,
        const float* __restrict__ skip, float* __restrict__ outF, int ldF,
        __nv_bfloat16* __restrict__ out3, int ld3, int M) {
    extern __shared__ char smem_raw[];
    char* smem = (char*)(((uintptr_t)smem_raw + 1023) & ~(uintptr_t)1023);
    const uint32_t tiles = smem_u32(smem);

    const int tid  = threadIdx.x;
    const int lane = tid & 31, wid = tid >> 5;
    const int m0   = blockIdx.x * 128;

    const int wm = (wid & 1) * 64;      // warp m offset (64-row half)
    const int wn = (wid >> 1) * 32;     // warp n offset (32-col quarter)

    float acc[4][4][4];
    #pragma unroll
    for (int i = 0; i < 4; i++)
        #pragma unroll
        for (int j = 0; j < 4; j++)
            #pragma unroll
            for (int q = 0; q < 4; q++) acc[i][j][q] = 0.f;

    const int nk0 = K0 / 64;
    const int nk  = nk0 + K1 / 64;

    // ldmatrix lane address components
    const int r_in = ((lane >> 3) & 1) * 8 + (lane & 7);
    const int ca8  = (lane >> 4) * 8;
    const int rb   = lane & 7;
    const int cb8  = ((lane >> 3) & 1) * 8;

    // stage s <- global chunk cn
    auto load_chunk = [&](int cn, int s) {
        if (cn < nk0) load_tiles(tiles, s, tid, m0, M, A0, lda0, B0, K0, cn * 64);
        else          load_tiles(tiles, s, tid, m0, M, A1, lda1, B1, K1, (cn - nk0) * 64);
    };

    load_chunk(0, 0);
    if (nk > 1) load_chunk(1, 1);

    #pragma unroll 1
    for (int c = 0; c < nk; c++) {
        if (c + 1 < nk) asm volatile("cp.async.wait_group 1;" ::: "memory");
        else            asm volatile("cp.async.wait_group 0;" ::: "memory");
        __syncthreads();
        if (c + 2 < nk) load_chunk(c + 2, (c + 2) % 3);

        uint32_t abase = tiles + (uint32_t)(c % 3) * 32768u;
        uint32_t bbase = abase + 16384u;
        #pragma unroll
        for (int ka = 0; ka < 4; ka++) {
            uint32_t a[4][4];
            #pragma unroll
            for (int ma = 0; ma < 4; ma++) {
                int r = wm + ma * 16 + r_in, cc = ka * 16 + ca8;
                ldm_x4(a[ma], abase + SW128((uint32_t)(r * 128 + cc * 2)));
            }
            uint32_t b[4][2];
            #pragma unroll
            for (int na = 0; na < 4; na++) {
                int r = wn + na * 8 + rb, cc = ka * 16 + cb8;
                ldm_x2(b[na], bbase + SW128((uint32_t)(r * 128 + cc * 2)));
            }
            #pragma unroll
            for (int ma = 0; ma < 4; ma++)
                #pragma unroll
                for (int na = 0; na < 4; na++)
                    mma_bf16(acc[ma][na], a[ma], b[na]);
        }
    }
    __syncthreads();

    // ---- park accumulators in smem C [128][132] fp32 (reuses tile smem) ----
    float* C = (float*)smem;
    #pragma unroll
    for (int ma = 0; ma < 4; ma++)
        #pragma unroll
        for (int na = 0; na < 4; na++) {
            int r0 = wm + ma * 16 + (lane >> 2);
            int cc = wn + na * 8 + 2 * (lane & 3);
            C[r0 * 132 + cc]           = acc[ma][na][0];
            C[r0 * 132 + cc + 1]       = acc[ma][na][1];
            C[(r0 + 8) * 132 + cc]     = acc[ma][na][2];
            C[(r0 + 8) * 132 + cc + 1] = acc[ma][na][3];
        }
    __syncthreads();

    // ---- epilogue: warp per row (16 rows per warp), lane owns 4 cols ----
    #pragma unroll 1
    for (int t = 0; t < 16; t++) {
        int rr  = wid + t * 8;
        int row = m0 + rr;
        if (row >= M) continue;
        float4 v = *reinterpret_cast<float4*>(C + rr * 132 + lane * 4);
        float4 bb = *reinterpret_cast<const float4*>(bias + lane * 4);
        v.x += bb.x; v.y += bb.y; v.z += bb.z; v.w += bb.w;
        if (MODE == 2) {
            float s  = v.x + v.y + v.z + v.w;
            float ss = v.x * v.x + v.y * v.y + v.z * v.z + v.w * v.w;
            #pragma unroll
            for (int off = 16; off; off >>= 1) {
                s  += __shfl_xor_sync(0xffffffffu, s,  off);
                ss += __shfl_xor_sync(0xffffffffu, ss, off);
            }
            float mu  = s * (1.0f / 128.0f);
            float var = ss * (1.0f / 128.0f) - mu * mu;
            float inv = rsqrtf(var + 1e-5f);
            float4 gg = *reinterpret_cast<const float4*>(lng + lane * 4);
            float4 ob = *reinterpret_cast<const float4*>(lnb + lane * 4);
            v.x = (v.x - mu) * inv * gg.x + ob.x;
            v.y = (v.y - mu) * inv * gg.y + ob.y;
            v.z = (v.z - mu) * inv * gg.z + ob.z;
            v.w = (v.w - mu) * inv * gg.w + ob.w;
            if (skip) {
                float4 sk = *reinterpret_cast<const float4*>(skip + (size_t)row * LD + lane * 4);
                v.x += sk.x; v.y += sk.y; v.z += sk.z; v.w += sk.w;
            }
        }
        if (MODE != 0) {
            v.x = fmaxf(v.x, 0.f); v.y = fmaxf(v.y, 0.f);
            v.z = fmaxf(v.z, 0.f); v.w = fmaxf(v.w, 0.f);
        }
        if (MODE == 0 || MODE == 2 || outF != nullptr) {
            *reinterpret_cast<float4*>(outF + (size_t)row * ldF + lane * 4) = v;
        }
        if (MODE != 0) {
            union { __nv_bfloat16 h[12]; uint2 u[3]; } p;
            float vv[4] = {v.x, v.y, v.z, v.w};
            #pragma unroll
            for (int jj = 0; jj < 4; jj++) {
                __nv_bfloat16 hi, lo; split2(vv[jj], hi, lo);
                p.h[3 * jj] = hi; p.h[3 * jj + 1] = hi; p.h[3 * jj + 2] = lo;
            }
            uint2* d = reinterpret_cast<uint2*>(out3 + (size_t)row * ld3 + lane * 12);
            d[0] = p.u[0]; d[1] = p.u[1]; d[2] = p.u[2];
        }
    }
}

// ---------------- launch ----------------
extern "C" void kernel_launch(void* const* d_in, const int* in_sizes, int n_in,
                              void* d_out, int out_size) {
    const float* x       = (const float*)d_in[0];
    const int*   ei      = (const int*)  d_in[1];
    const float* emb_W   = (const float*)d_in[2];
    const float* emb_b   = (const float*)d_in[3];
    const float* lin_l_W = (const float*)d_in[4];
    const float* lin_l_b = (const float*)d_in[5];
    const float* lin_r_W = (const float*)d_in[6];
    const float* ln_g    = (const float*)d_in[7];
    const float* ln_b    = (const float*)d_in[8];
    const float* fus_W1  = (const float*)d_in[9];
    const float* fus_b1  = (const float*)d_in[10];
    const float* fus_W2  = (const float*)d_in[11];
    const float* fus_b2  = (const float*)d_in[12];
    float* out = (float*)d_out;

    const int M = in_sizes[0] / INDIM;
    const int E = in_sizes[1] / 2;

    float *REPS; __nv_bfloat16 *REPS3, *X3, *AGG3, *TMP3, *W3;
    int *CNT;
    cudaGetSymbolAddress((void**)&REPS,  g_REPS);
    cudaGetSymbolAddress((void**)&REPS3, g_REPS3);
    cudaGetSymbolAddress((void**)&X3,    g_X3);
    cudaGetSymbolAddress((void**)&AGG3,  g_AGG3);
    cudaGetSymbolAddress((void**)&TMP3,  g_TMP3);
    cudaGetSymbolAddress((void**)&W3,    g_W3);
    cudaGetSymbolAddress((void**)&CNT,   g_cnt);

    cudaFuncSetAttribute(k_mgemm<0>, cudaFuncAttributeMaxDynamicSharedMemorySize, DSMEM);
    cudaFuncSetAttribute(k_mgemm<1>, cudaFuncAttributeMaxDynamicSharedMemorySize, DSMEM);
    cudaFuncSetAttribute(k_mgemm<2>, cudaFuncAttributeMaxDynamicSharedMemorySize, DSMEM);

    const int* src = ei;
    const int* dst = ei + E;

    cudaMemsetAsync(CNT, 0, (size_t)M * sizeof(int), 0);

    // CSR build (scan also seeds g_cursor with rowptr)
    k_count<<<(E + 255) / 256, 256>>>(dst, E);
    k_scan<<<1, 1024>>>(M);
    k_fill<<<(E + 255) / 256, 256>>>(src, dst, E);

    // prep: all weights (one launch) + x split
    k_wsplit_all<<<(270336 + 255) / 256, 256>>>(emb_W, lin_l_W, lin_r_W, fus_W1, fus_W2);
    k_xsplit<<<((M * 80) + 255) / 256, 256>>>(x, X3, M);

    const int G = (M + 127) / 128;
    const int warp_grid = (M + 7) / 8;

    // embedding: relu(x@W+b) -> REPS slice0 fp32 + REPS3 slice0 split
    k_mgemm<1><<<G, 256, DSMEM>>>(X3, K3_X, W3 + OFF_EMBW, K3_X,
                                  nullptr, 0, nullptr, 0,
                                  emb_b, nullptr, nullptr, nullptr,
                                  REPS, LD, REPS3, LD3, M);

    for (int i = 0; i < NL; i++) {
        k_agg<<<warp_grid, 256>>>(REPS + (size_t)i * HID, AGG3, M);
        k_mgemm<2><<<G, 256, DSMEM>>>(AGG3, K3_H, W3 + OFF_LINL + (size_t)i * 49152, K3_H,
                                      REPS3 + (size_t)i * K3_H, LD3,
                                      W3 + OFF_LINR + (size_t)i * 49152, K3_H,
                                      lin_l_b + (size_t)i * HID,
                                      ln_g + (size_t)i * HID, ln_b + (size_t)i * HID,
                                      (i > 0) ? (REPS + (size_t)i * HID) : nullptr,
                                      REPS + (size_t)(i + 1) * HID, LD,
                                      REPS3 + (size_t)(i + 1) * K3_H, LD3, M);
    }

    // fusion MLP
    k_mgemm<1><<<G, 256, DSMEM>>>(REPS3, LD3, W3 + OFF_FUS1, K3_F,
                                  nullptr, 0, nullptr, 0,
                                  fus_b1, nullptr, nullptr, nullptr,
                                  nullptr, 0, TMP3, K3_H, M);
    k_mgemm<0><<<G, 256, DSMEM>>>(TMP3, K3_H, W3 + OFF_FUS2, K3_H,
                                  nullptr, 0, nullptr, 0,
                                  fus_b2, nullptr, nullptr, nullptr,
                                  out, HID, nullptr, 0, M);
}

// round 5
// speedup vs baseline: 1.8609x; 1.0056x over previous
#include <cuda_runtime.h>
#include <cuda_bf16.h>
#include <cstdint>
#include <math.h>

#define NN    50000
#define EE    800000
#define INDIM 300
#define HID   128
#define NL    4
#define LD    640        // (NL+1)*HID fp32 reps row
#define LD3   1920       // 3*LD  split-bf16 reps row
#define K3_X  960        // padded 3*300 (300->320 triples)
#define K3_H  384        // 3*128
#define K3_F  1920       // 3*640

// weight pack offsets (elements)
#define OFF_EMBW 0
#define OFF_LINL 122880
#define OFF_LINR 319488
#define OFF_FUS1 516096
#define OFF_FUS2 761856
#define W3_TOTAL 811008

// dynamic smem: 1024 align slack + max(3 tile stages 96KB, C 128*132*4=67584)
#define DSMEM (1024 + 98304)

// ---------------- scratch (device globals) ----------------
__device__ __align__(256) float          g_REPS [(size_t)NN * LD];
__device__ __align__(256) __nv_bfloat16  g_REPS3[(size_t)NN * LD3];
__device__ __align__(256) __nv_bfloat16  g_HB   [(size_t)NN * HID];   // bf16 gather source
__device__ __align__(256) __nv_bfloat16  g_X3   [(size_t)NN * K3_X];
__device__ __align__(256) __nv_bfloat16  g_AGG3 [(size_t)NN * K3_H];
__device__ __align__(256) __nv_bfloat16  g_TMP3 [(size_t)NN * K3_H];
__device__ __align__(256) __nv_bfloat16  g_W3   [W3_TOTAL];
__device__ float g_invdeg[NN];
__device__ int   g_cnt[NN];
__device__ int   g_cursor[NN];
__device__ int   g_rowptr[NN + 1];
__device__ int   g_col[EE];

// ---------------- helpers ----------------
__device__ __forceinline__ uint32_t smem_u32(const void* p) {
    uint32_t a;
    asm("{ .reg .u64 t; cvta.to.shared.u64 t, %1; cvt.u32.u64 %0, t; }" : "=r"(a) : "l"(p));
    return a;
}
#define SW128(b) ((b) ^ (((b) >> 3) & 0x70))

__device__ __forceinline__ void cp16(uint32_t dst, const void* src, int sz) {
    asm volatile("cp.async.cg.shared.global [%0], [%1], 16, %2;"
                 :: "r"(dst), "l"(src), "r"(sz) : "memory");
}
__device__ __forceinline__ void ldm_x4(uint32_t* r, uint32_t addr) {
    asm volatile("ldmatrix.sync.aligned.m8n8.x4.shared.b16 {%0,%1,%2,%3}, [%4];"
                 : "=r"(r[0]), "=r"(r[1]), "=r"(r[2]), "=r"(r[3]) : "r"(addr));
}
__device__ __forceinline__ void ldm_x2(uint32_t* r, uint32_t addr) {
    asm volatile("ldmatrix.sync.aligned.m8n8.x2.shared.b16 {%0,%1}, [%2];"
                 : "=r"(r[0]), "=r"(r[1]) : "r"(addr));
}
__device__ __forceinline__ void mma_bf16(float* c, const uint32_t* a, const uint32_t* b) {
    asm volatile(
        "mma.sync.aligned.m16n8k16.row.col.f32.bf16.bf16.f32 "
        "{%0,%1,%2,%3}, {%4,%5,%6,%7}, {%8,%9}, {%0,%1,%2,%3};"
        : "+f"(c[0]), "+f"(c[1]), "+f"(c[2]), "+f"(c[3])
        : "r"(a[0]), "r"(a[1]), "r"(a[2]), "r"(a[3]), "r"(b[0]), "r"(b[1]));
}
__device__ __forceinline__ void split2(float v, __nv_bfloat16& hi, __nv_bfloat16& lo) {
    hi = __float2bfloat16(v);
    lo = __float2bfloat16(v - __bfloat162float(hi));
}

// ---------------- CSR build ----------------
__global__ void k_count(const int* __restrict__ dst, int E) {
    int i = blockIdx.x * blockDim.x + threadIdx.x;
    if (i < E) atomicAdd(&g_cnt[dst[i]], 1);
}

__global__ void __launch_bounds__(1024) k_scan(int M) {
    const int T = 1024;
    int t = threadIdx.x;
    int per = (M + T - 1) / T;
    int beg = t * per;
    int end = min(beg + per, M);
    int sum = 0;
    for (int i = beg; i < end; i++) sum += g_cnt[i];

    int lane = t & 31, wid = t >> 5;
    int v = sum;
    #pragma unroll
    for (int o = 1; o < 32; o <<= 1) {
        int u = __shfl_up_sync(0xffffffffu, v, o);
        if (lane >= o) v += u;
    }
    __shared__ int ws[32];
    if (lane == 31) ws[wid] = v;
    __syncthreads();
    if (wid == 0) {
        int wv = ws[lane];
        #pragma unroll
        for (int o = 1; o < 32; o <<= 1) {
            int u = __shfl_up_sync(0xffffffffu, wv, o);
            if (lane >= o) wv += u;
        }
        ws[lane] = wv;
    }
    __syncthreads();
    int run = v - sum + (wid ? ws[wid - 1] : 0);
    for (int i = beg; i < end; i++) {
        int c = g_cnt[i];
        g_rowptr[i] = run;
        g_cursor[i] = run;
        g_invdeg[i] = 1.0f / fmaxf((float)c, 1.0f);
        run += c;
    }
    if (t == T - 1) g_rowptr[M] = run;
}

__global__ void k_fill(const int* __restrict__ src, const int* __restrict__ dst, int E) {
    int i = blockIdx.x * blockDim.x + threadIdx.x;
    if (i < E) {
        int pos = atomicAdd(&g_cursor[dst[i]], 1);
        g_col[pos] = src[i];
    }
}

// ---------------- weight prep (one launch) ----------------
__device__ __forceinline__ void wsplit_one(const float* W, __nv_bfloat16* o3,
                                           int idx, int K, int Kp) {
    int n = idx / Kp, kp = idx % Kp;
    __nv_bfloat16 hi, lo;
    if (kp < K) {
        split2(W[(size_t)kp * 128 + n], hi, lo);
    } else {
        hi = __float2bfloat16(0.f); lo = hi;
    }
    __nv_bfloat16* o = o3 + (size_t)n * (3 * Kp) + 3 * kp;
    o[0] = hi; o[1] = lo; o[2] = hi;
}

__global__ void k_wsplit_all(const float* __restrict__ emb_W,
                             const float* __restrict__ lin_l_W,
                             const float* __restrict__ lin_r_W,
                             const float* __restrict__ fus_W1,
                             const float* __restrict__ fus_W2) {
    int w = blockIdx.x * blockDim.x + threadIdx.x;
    if (w < 40960) {
        wsplit_one(emb_W, g_W3 + OFF_EMBW, w, 300, 320);
    } else if (w < 106496) {
        int u = w - 40960, i = u >> 14;
        wsplit_one(lin_l_W + (size_t)i * 16384, g_W3 + OFF_LINL + (size_t)i * 49152,
                   u & 16383, 128, 128);
    } else if (w < 172032) {
        int u = w - 106496, i = u >> 14;
        wsplit_one(lin_r_W + (size_t)i * 16384, g_W3 + OFF_LINR + (size_t)i * 49152,
                   u & 16383, 128, 128);
    } else if (w < 253952) {
        wsplit_one(fus_W1, g_W3 + OFF_FUS1, w - 172032, 640, 640);
    } else if (w < 270336) {
        wsplit_one(fus_W2, g_W3 + OFF_FUS2, w - 253952, 128, 128);
    }
}

// x [M,300] fp32 -> X3 [M,960] bf16, A-pattern [hi,hi,lo], zero pad
__global__ void k_xsplit(const float* __restrict__ x, __nv_bfloat16* __restrict__ out, int M) {
    int idx = blockIdx.x * blockDim.x + threadIdx.x;
    int row = idx / 80, g = idx % 80;
    if (row >= M) return;
    float vv[4] = {0.f, 0.f, 0.f, 0.f};
    if (g < 75) {
        float4 t = *reinterpret_cast<const float4*>(x + (size_t)row * INDIM + g * 4);
        vv[0] = t.x; vv[1] = t.y; vv[2] = t.z; vv[3] = t.w;
    }
    union { __nv_bfloat16 h[12]; uint2 u[3]; } p;
    #pragma unroll
    for (int j = 0; j < 4; j++) {
        __nv_bfloat16 hi, lo; split2(vv[j], hi, lo);
        p.h[3 * j] = hi; p.h[3 * j + 1] = hi; p.h[3 * j + 2] = lo;
    }
    uint2* d = reinterpret_cast<uint2*>(out + (size_t)row * K3_X + g * 12);
    d[0] = p.u[0]; d[1] = p.u[1]; d[2] = p.u[2];
}

// ---------------- mean aggregation from bf16 rows -> split bf16 ----------------
__global__ void k_agg(const __nv_bfloat16* __restrict__ HB /* [N,128] bf16 */,
                      __nv_bfloat16* __restrict__ out3, int M) {
    int gw   = (blockIdx.x * blockDim.x + threadIdx.x) >> 5;
    int lane = threadIdx.x & 31;
    if (gw >= M) return;
    int beg = g_rowptr[gw], end = g_rowptr[gw + 1];
    float a0 = 0.f, a1 = 0.f, a2 = 0.f, a3 = 0.f;
    float b0 = 0.f, b1 = 0.f, b2 = 0.f, b3 = 0.f;
    union U { uint2 u; __nv_bfloat162 h2[2]; };
    for (int base = beg; base < end; base += 32) {
        int idx = (base + lane < end) ? g_col[base + lane] : 0;
        int cnt = min(32, end - base);
        int j = 0;
        for (; j + 3 < cnt; j += 4) {
            int s0 = __shfl_sync(0xffffffffu, idx, j);
            int s1 = __shfl_sync(0xffffffffu, idx, j + 1);
            int s2 = __shfl_sync(0xffffffffu, idx, j + 2);
            int s3 = __shfl_sync(0xffffffffu, idx, j + 3);
            U u0, u1, u2, u3;
            u0.u = *reinterpret_cast<const uint2*>(HB + (size_t)s0 * HID + lane * 4);
            u1.u = *reinterpret_cast<const uint2*>(HB + (size_t)s1 * HID + lane * 4);
            u2.u = *reinterpret_cast<const uint2*>(HB + (size_t)s2 * HID + lane * 4);
            u3.u = *reinterpret_cast<const uint2*>(HB + (size_t)s3 * HID + lane * 4);
            float2 p;
            p = __bfloat1622float2(u0.h2[0]); a0 += p.x; a1 += p.y;
            p = __bfloat1622float2(u0.h2[1]); a2 += p.x; a3 += p.y;
            p = __bfloat1622float2(u1.h2[0]); b0 += p.x; b1 += p.y;
            p = __bfloat1622float2(u1.h2[1]); b2 += p.x; b3 += p.y;
            p = __bfloat1622float2(u2.h2[0]); a0 += p.x; a1 += p.y;
            p = __bfloat1622float2(u2.h2[1]); a2 += p.x; a3 += p.y;
            p = __bfloat1622float2(u3.h2[0]); b0 += p.x; b1 += p.y;
            p = __bfloat1622float2(u3.h2[1]); b2 += p.x; b3 += p.y;
        }
        for (; j < cnt; j++) {
            int s = __shfl_sync(0xffffffffu, idx, j);
            U u; u.u = *reinterpret_cast<const uint2*>(HB + (size_t)s * HID + lane * 4);
            float2 p;
            p = __bfloat1622float2(u.h2[0]); a0 += p.x; a1 += p.y;
            p = __bfloat1622float2(u.h2[1]); a2 += p.x; a3 += p.y;
        }
    }
    a0 += b0; a1 += b1; a2 += b2; a3 += b3;
    float w = g_invdeg[gw];
    float m[4] = {a0 * w, a1 * w, a2 * w, a3 * w};
    union { __nv_bfloat16 h[12]; uint2 u[3]; } p;
    #pragma unroll
    for (int j = 0; j < 4; j++) {
        __nv_bfloat16 hi, lo; split2(m[j], hi, lo);
        p.h[3 * j] = hi; p.h[3 * j + 1] = hi; p.h[3 * j + 2] = lo;
    }
    uint2* d = reinterpret_cast<uint2*>(out3 + (size_t)gw * K3_H + lane * 12);
    d[0] = p.u[0]; d[1] = p.u[1]; d[2] = p.u[2];
}

// ---------------- tile loader (cp.async, SW128 swizzle) ----------------
__device__ __forceinline__ void load_tiles(uint32_t tiles, int s, int tid, int m0, int M,
                                           const __nv_bfloat16* A, int lda,
                                           const __nv_bfloat16* B, int K, int k0) {
    uint32_t abase = tiles + (uint32_t)s * 32768u;
    uint32_t bbase = abase + 16384u;
    #pragma unroll
    for (int i = 0; i < 4; i++) {
        int v = tid + i * 256;
        int r = v >> 3, ch = v & 7;
        uint32_t bo = (uint32_t)(r * 128 + ch * 16);
        int row = m0 + r;
        int rc = row < M ? row : 0;
        const __nv_bfloat16* src = A + (size_t)rc * lda + k0 + ch * 8;
        cp16(abase + SW128(bo), src, row < M ? 16 : 0);
    }
    #pragma unroll
    for (int i = 0; i < 4; i++) {
        int v = tid + i * 256;
        int r = v >> 3, ch = v & 7;
        uint32_t bo = (uint32_t)(r * 128 + ch * 16);
        cp16(bbase + SW128(bo), B + (size_t)r * K + k0 + ch * 8, 16);
    }
    asm volatile("cp.async.commit_group;" ::: "memory");
}

// ---------------- mma.sync GEMM, 128x128 tile, BK=64, 3-stage, dual-segment ----------------
// MODE 0: out = acc + bias                      -> outF
// MODE 1: v = relu(acc+bias)                    -> [outF] + [hb] + split out3
// MODE 2: v = LN(acc+bias)*g+b (+skip), relu    -> [outF] + [hb] + split out3
template <int MODE>
__global__ void __launch_bounds__(256)
k_mgemm(const __nv_bfloat16* __restrict__ A0, int lda0, const __nv_bfloat16* __restrict__ B0, int K0,
        const __nv_bfloat16* __restrict__ A1, int lda1, const __nv_bfloat16* __restrict__ B1, int K1,
        const float* __restrict__ bias, const float* __restrict__ lng, const float* __restrict__ lnb,
        const float* __restrict__ skip, float* __restrict__ outF, int ldF,
        __nv_bfloat16* __restrict__ hb,
        __nv_bfloat16* __restrict__ out3, int ld3, int M) {
    extern __shared__ char smem_raw[];
    char* smem = (char*)(((uintptr_t)smem_raw + 1023) & ~(uintptr_t)1023);
    const uint32_t tiles = smem_u32(smem);

    const int tid  = threadIdx.x;
    const int lane = tid & 31, wid = tid >> 5;
    const int m0   = blockIdx.x * 128;

    const int wm = (wid & 1) * 64;
    const int wn = (wid >> 1) * 32;

    float acc[4][4][4];
    #pragma unroll
    for (int i = 0; i < 4; i++)
        #pragma unroll
        for (int j = 0; j < 4; j++)
            #pragma unroll
            for (int q = 0; q < 4; q++) acc[i][j][q] = 0.f;

    const int nk0 = K0 / 64;
    const int nk  = nk0 + K1 / 64;

    const int r_in = ((lane >> 3) & 1) * 8 + (lane & 7);
    const int ca8  = (lane >> 4) * 8;
    const int rb   = lane & 7;
    const int cb8  = ((lane >> 3) & 1) * 8;

    auto load_chunk = [&](int cn, int s) {
        if (cn < nk0) load_tiles(tiles, s, tid, m0, M, A0, lda0, B0, K0, cn * 64);
        else          load_tiles(tiles, s, tid, m0, M, A1, lda1, B1, K1, (cn - nk0) * 64);
    };

    load_chunk(0, 0);
    if (nk > 1) load_chunk(1, 1);

    #pragma unroll 1
    for (int c = 0; c < nk; c++) {
        if (c + 1 < nk) asm volatile("cp.async.wait_group 1;" ::: "memory");
        else            asm volatile("cp.async.wait_group 0;" ::: "memory");
        __syncthreads();
        if (c + 2 < nk) load_chunk(c + 2, (c + 2) % 3);

        uint32_t abase = tiles + (uint32_t)(c % 3) * 32768u;
        uint32_t bbase = abase + 16384u;
        #pragma unroll
        for (int ka = 0; ka < 4; ka++) {
            uint32_t a[4][4];
            #pragma unroll
            for (int ma = 0; ma < 4; ma++) {
                int r = wm + ma * 16 + r_in, cc = ka * 16 + ca8;
                ldm_x4(a[ma], abase + SW128((uint32_t)(r * 128 + cc * 2)));
            }
            uint32_t b[4][2];
            #pragma unroll
            for (int na = 0; na < 4; na++) {
                int r = wn + na * 8 + rb, cc = ka * 16 + cb8;
                ldm_x2(b[na], bbase + SW128((uint32_t)(r * 128 + cc * 2)));
            }
            #pragma unroll
            for (int ma = 0; ma < 4; ma++)
                #pragma unroll
                for (int na = 0; na < 4; na++)
                    mma_bf16(acc[ma][na], a[ma], b[na]);
        }
    }
    __syncthreads();

    // park accumulators in smem C [128][132] fp32
    float* C = (float*)smem;
    #pragma unroll
    for (int ma = 0; ma < 4; ma++)
        #pragma unroll
        for (int na = 0; na < 4; na++) {
            int r0 = wm + ma * 16 + (lane >> 2);
            int cc = wn + na * 8 + 2 * (lane & 3);
            C[r0 * 132 + cc]           = acc[ma][na][0];
            C[r0 * 132 + cc + 1]       = acc[ma][na][1];
            C[(r0 + 8) * 132 + cc]     = acc[ma][na][2];
            C[(r0 + 8) * 132 + cc + 1] = acc[ma][na][3];
        }
    __syncthreads();

    // epilogue: warp per row
    #pragma unroll 1
    for (int t = 0; t < 16; t++) {
        int rr  = wid + t * 8;
        int row = m0 + rr;
        if (row >= M) continue;
        float4 v = *reinterpret_cast<float4*>(C + rr * 132 + lane * 4);
        float4 bb = *reinterpret_cast<const float4*>(bias + lane * 4);
        v.x += bb.x; v.y += bb.y; v.z += bb.z; v.w += bb.w;
        if (MODE == 2) {
            float s  = v.x + v.y + v.z + v.w;
            float ss = v.x * v.x + v.y * v.y + v.z * v.z + v.w * v.w;
            #pragma unroll
            for (int off = 16; off; off >>= 1) {
                s  += __shfl_xor_sync(0xffffffffu, s,  off);
                ss += __shfl_xor_sync(0xffffffffu, ss, off);
            }
            float mu  = s * (1.0f / 128.0f);
            float var = ss * (1.0f / 128.0f) - mu * mu;
            float inv = rsqrtf(var + 1e-5f);
            float4 gg = *reinterpret_cast<const float4*>(lng + lane * 4);
            float4 ob = *reinterpret_cast<const float4*>(lnb + lane * 4);
            v.x = (v.x - mu) * inv * gg.x + ob.x;
            v.y = (v.y - mu) * inv * gg.y + ob.y;
            v.z = (v.z - mu) * inv * gg.z + ob.z;
            v.w = (v.w - mu) * inv * gg.w + ob.w;
            if (skip) {
                float4 sk = *reinterpret_cast<const float4*>(skip + (size_t)row * LD + lane * 4);
                v.x += sk.x; v.y += sk.y; v.z += sk.z; v.w += sk.w;
            }
        }
        if (MODE != 0) {
            v.x = fmaxf(v.x, 0.f); v.y = fmaxf(v.y, 0.f);
            v.z = fmaxf(v.z, 0.f); v.w = fmaxf(v.w, 0.f);
        }
        if (outF) {
            *reinterpret_cast<float4*>(outF + (size_t)row * ldF + lane * 4) = v;
        }
        if (MODE != 0) {
            if (hb) {
                union { __nv_bfloat162 h2[2]; uint2 u; } q;
                q.h2[0] = __floats2bfloat162_rn(v.x, v.y);
                q.h2[1] = __floats2bfloat162_rn(v.z, v.w);
                *reinterpret_cast<uint2*>(hb + (size_t)row * HID + lane * 4) = q.u;
            }
            union { __nv_bfloat16 h[12]; uint2 u[3]; } p;
            float vv[4] = {v.x, v.y, v.z, v.w};
            #pragma unroll
            for (int jj = 0; jj < 4; jj++) {
                __nv_bfloat16 hi, lo; split2(vv[jj], hi, lo);
                p.h[3 * jj] = hi; p.h[3 * jj + 1] = hi; p.h[3 * jj + 2] = lo;
            }
            uint2* d = reinterpret_cast<uint2*>(out3 + (size_t)row * ld3 + lane * 12);
            d[0] = p.u[0]; d[1] = p.u[1]; d[2] = p.u[2];
        }
    }
}

// ---------------- launch ----------------
extern "C" void kernel_launch(void* const* d_in, const int* in_sizes, int n_in,
                              void* d_out, int out_size) {
    const float* x       = (const float*)d_in[0];
    const int*   ei      = (const int*)  d_in[1];
    const float* emb_W   = (const float*)d_in[2];
    const float* emb_b   = (const float*)d_in[3];
    const float* lin_l_W = (const float*)d_in[4];
    const float* lin_l_b = (const float*)d_in[5];
    const float* lin_r_W = (const float*)d_in[6];
    const float* ln_g    = (const float*)d_in[7];
    const float* ln_b    = (const float*)d_in[8];
    const float* fus_W1  = (const float*)d_in[9];
    const float* fus_b1  = (const float*)d_in[10];
    const float* fus_W2  = (const float*)d_in[11];
    const float* fus_b2  = (const float*)d_in[12];
    float* out = (float*)d_out;

    const int M = in_sizes[0] / INDIM;
    const int E = in_sizes[1] / 2;

    float *REPS; __nv_bfloat16 *REPS3, *HB, *X3, *AGG3, *TMP3, *W3;
    int *CNT;
    cudaGetSymbolAddress((void**)&REPS,  g_REPS);
    cudaGetSymbolAddress((void**)&REPS3, g_REPS3);
    cudaGetSymbolAddress((void**)&HB,    g_HB);
    cudaGetSymbolAddress((void**)&X3,    g_X3);
    cudaGetSymbolAddress((void**)&AGG3,  g_AGG3);
    cudaGetSymbolAddress((void**)&TMP3,  g_TMP3);
    cudaGetSymbolAddress((void**)&W3,    g_W3);
    cudaGetSymbolAddress((void**)&CNT,   g_cnt);

    cudaFuncSetAttribute(k_mgemm<0>, cudaFuncAttributeMaxDynamicSharedMemorySize, DSMEM);
    cudaFuncSetAttribute(k_mgemm<1>, cudaFuncAttributeMaxDynamicSharedMemorySize, DSMEM);
    cudaFuncSetAttribute(k_mgemm<2>, cudaFuncAttributeMaxDynamicSharedMemorySize, DSMEM);

    // side stream + fork/join events (created once, first call is outside capture)
    static cudaStream_t s1 = []() {
        cudaStream_t s; cudaStreamCreateWithFlags(&s, cudaStreamNonBlocking); return s;
    }();
    static cudaEvent_t evFork = []() {
        cudaEvent_t e; cudaEventCreateWithFlags(&e, cudaEventDisableTiming); return e;
    }();
    static cudaEvent_t evJoin = []() {
        cudaEvent_t e; cudaEventCreateWithFlags(&e, cudaEventDisableTiming); return e;
    }();

    const int* src = ei;
    const int* dst = ei + E;

    const int G = (M + 127) / 128;
    const int warp_grid = (M + 7) / 8;

    // ---- fork: side stream does prep + embedding GEMM ----
    cudaEventRecord(evFork, 0);
    cudaStreamWaitEvent(s1, evFork, 0);

    k_wsplit_all<<<(270336 + 255) / 256, 256, 0, s1>>>(emb_W, lin_l_W, lin_r_W, fus_W1, fus_W2);
    k_xsplit<<<((M * 80) + 255) / 256, 256, 0, s1>>>(x, X3, M);
    // embedding: relu(x@W+b) -> HB (bf16 gather source) + REPS3 slice0
    k_mgemm<1><<<G, 256, DSMEM, s1>>>(X3, K3_X, W3 + OFF_EMBW, K3_X,
                                      nullptr, 0, nullptr, 0,
                                      emb_b, nullptr, nullptr, nullptr,
                                      nullptr, 0, HB, REPS3, LD3, M);
    cudaEventRecord(evJoin, s1);

    // ---- main stream: CSR build ----
    cudaMemsetAsync(CNT, 0, (size_t)M * sizeof(int), 0);
    k_count<<<(E + 255) / 256, 256>>>(dst, E);
    k_scan<<<1, 1024>>>(M);
    k_fill<<<(E + 255) / 256, 256>>>(src, dst, E);

    cudaStreamWaitEvent(0, evJoin, 0);

    // ---- layers ----
    for (int i = 0; i < NL; i++) {
        k_agg<<<warp_grid, 256>>>(HB, AGG3, M);
        k_mgemm<2><<<G, 256, DSMEM>>>(AGG3, K3_H, W3 + OFF_LINL + (size_t)i * 49152, K3_H,
                                      REPS3 + (size_t)i * K3_H, LD3,
                                      W3 + OFF_LINR + (size_t)i * 49152, K3_H,
                                      lin_l_b + (size_t)i * HID,
                                      ln_g + (size_t)i * HID, ln_b + (size_t)i * HID,
                                      (i > 0) ? (REPS + (size_t)i * HID) : nullptr,
                                      (i + 1 <= 3) ? (REPS + (size_t)(i + 1) * HID) : nullptr, LD,
                                      (i + 1 < NL) ? HB : nullptr,
                                      REPS3 + (size_t)(i + 1) * K3_H, LD3, M);
    }

    // ---- fusion MLP ----
    k_mgemm<1><<<G, 256, DSMEM>>>(REPS3, LD3, W3 + OFF_FUS1, K3_F,
                                  nullptr, 0, nullptr, 0,
                                  fus_b1, nullptr, nullptr, nullptr,
                                  nullptr, 0, nullptr, TMP3, K3_H, M);
    k_mgemm<0><<<G, 256, DSMEM>>>(TMP3, K3_H, W3 + OFF_FUS2, K3_H,
                                  nullptr, 0, nullptr, 0,
                                  fus_b2, nullptr, nullptr, nullptr,
                                  out, HID, nullptr, nullptr, 0, M);
}